// round 5
// baseline (speedup 1.0000x reference)
#include <cuda_runtime.h>
#include <cuda_bf16.h>
#include <cstdint>
#include <cstddef>

// ============================================================================
// Problem constants
// ============================================================================
#define NLAYER 4
#define BATCH  4096
#define DIM    1024
#define TM     128          // CTA tile M (batch rows)
#define TN     128          // CTA tile N = 32 d-cols x 4 gates, interleaved
#define BK     32           // K per chunk
#define NCHUNK 64           // 2048 / 32
#define THREADS 512         // 16 warps: 4(M) x 4(N) warp grid, 32x32 warp tiles

// SMEM: padded rows, 32 bf16 = 64B data + 16B pad = 80B stride.
// ldmatrix row addrs (stride 80) mod 128 are all-distinct -> conflict-free.
#define ROWB   80
#define REGION (TM * ROWB)          // 10240 bytes (one 128x32 bf16 tile)
#define A_HI   0
#define A_LO   (REGION)
#define B_HI   (2 * REGION)
#define B_LO   (3 * REGION)
#define STAGE  (4 * REGION)         // 40960
#define SMEM_TOTAL (2 * STAGE)      // 81920 (double buffered)

// Epilogue reuses the stage buffers (after final sync):
#define EP_HS   0
#define EP_CS   16384
#define EP_CIN  32768

// ============================================================================
// Helpers
// ============================================================================
__device__ __forceinline__ uint32_t smem_u32(const void* p) {
    uint32_t a;
    asm("{ .reg .u64 t; cvta.to.shared.u64 t, %1; cvt.u32.u64 %0, t; }"
        : "=r"(a) : "l"(p));
    return a;
}

__device__ __forceinline__ void ldm4(uint32_t* r, uint32_t addr) {
    asm volatile("ldmatrix.sync.aligned.m8n8.x4.shared.b16 {%0,%1,%2,%3}, [%4];"
                 : "=r"(r[0]), "=r"(r[1]), "=r"(r[2]), "=r"(r[3]) : "r"(addr));
}

__device__ __forceinline__ void mma16816(float* c, const uint32_t* a, const uint32_t* b) {
    asm volatile(
        "mma.sync.aligned.m16n8k16.row.col.f32.bf16.bf16.f32 "
        "{%0,%1,%2,%3}, {%4,%5,%6,%7}, {%8,%9}, {%0,%1,%2,%3};"
        : "+f"(c[0]), "+f"(c[1]), "+f"(c[2]), "+f"(c[3])
        : "r"(a[0]), "r"(a[1]), "r"(a[2]), "r"(a[3]), "r"(b[0]), "r"(b[1]));
}

__device__ __forceinline__ float sigmoidf_(float x) {
    return __fdividef(1.0f, 1.0f + __expf(-x));
}
__device__ __forceinline__ float tanhf_(float x) {
    return 2.0f * sigmoidf_(2.0f * x) - 1.0f;
}

// fp32 -> (bf16 hi, bf16 lo) split of a float4, stored to padded smem rows.
__device__ __forceinline__ void split_store(char* hi_base, char* lo_base,
                                            int row, int c4, float4 v) {
    __nv_bfloat16 h0 = __float2bfloat16_rn(v.x);
    __nv_bfloat16 h1 = __float2bfloat16_rn(v.y);
    __nv_bfloat16 h2 = __float2bfloat16_rn(v.z);
    __nv_bfloat16 h3 = __float2bfloat16_rn(v.w);
    __nv_bfloat16 l0 = __float2bfloat16_rn(v.x - __bfloat162float(h0));
    __nv_bfloat16 l1 = __float2bfloat16_rn(v.y - __bfloat162float(h1));
    __nv_bfloat16 l2 = __float2bfloat16_rn(v.z - __bfloat162float(h2));
    __nv_bfloat16 l3 = __float2bfloat16_rn(v.w - __bfloat162float(h3));
    uint32_t hi01 = ((uint32_t)__bfloat16_as_ushort(h1) << 16) | __bfloat16_as_ushort(h0);
    uint32_t hi23 = ((uint32_t)__bfloat16_as_ushort(h3) << 16) | __bfloat16_as_ushort(h2);
    uint32_t lo01 = ((uint32_t)__bfloat16_as_ushort(l1) << 16) | __bfloat16_as_ushort(l0);
    uint32_t lo23 = ((uint32_t)__bfloat16_as_ushort(l3) << 16) | __bfloat16_as_ushort(l2);
    uint32_t off = (uint32_t)(row * ROWB + c4 * 8);
    *(uint2*)(hi_base + off) = make_uint2(hi01, hi23);
    *(uint2*)(lo_base + off) = make_uint2(lo01, lo23);
}

// ============================================================================
// Scratch: gathered embedding x0 = emb[tokens]  [BATCH, DIM] fp32
// ============================================================================
__device__ float g_x0[(size_t)BATCH * DIM];

__global__ void gather_kernel(const float* __restrict__ emb,
                              const int* __restrict__ tokens) {
    int b = blockIdx.x;
    int t = tokens[b];
    const float4* src = (const float4*)(emb + (size_t)t * DIM);
    float4* dst = (float4*)(g_x0 + (size_t)b * DIM);
    for (int i = threadIdx.x; i < DIM / 4; i += blockDim.x) dst[i] = src[i];
}

// ============================================================================
// Fused LSTM layer: gates GEMM (3xBF16-split mma.sync) + cell update.
// Grid (32 n-blocks, 32 m-blocks), 512 threads.
// N col j (0..127): gate = j&3, d = d0 + (j>>2).
// ============================================================================
__global__ void __launch_bounds__(THREADS, 1)
lstm_layer_kernel(const float* __restrict__ X,     // layer input; nullptr -> g_x0
                  const float* __restrict__ Hin,
                  const float* __restrict__ Wxl,   // [4*DIM, DIM]
                  const float* __restrict__ Whl,
                  const float* __restrict__ Cin,
                  float* __restrict__ Hout,
                  float* __restrict__ Cout) {
    extern __shared__ __align__(128) char smem[];
    const uint32_t sb = smem_u32(smem);
    const int tid  = threadIdx.x;
    const int wid  = tid >> 5;
    const int lane = tid & 31;
    const int m0 = blockIdx.y * TM;
    const int d0 = blockIdx.x * (TN / 4);
    const float* Xp = X ? X : g_x0;

    const int wm = wid & 3;          // warp M index (0..3)
    const int wn = wid >> 2;         // warp N index (0..3)

    // ldmatrix lane addressing pieces
    const int l15 = lane & 15;
    const int l7  = lane & 7;
    const uint32_t aOff  = ((lane >> 4) & 1) << 4;   // 0/16
    const int      bSel  = (lane >> 4) & 1;          // which n8-tile of the pair
    const uint32_t bHalf = ((lane >> 3) & 1) << 4;   // 0/16

    // per-thread global load slots: 2 A rows + 2 B rows, one float4 each
    const int rA = tid >> 3;          // 0..63
    const int c4 = tid & 7;           // float4 index within 32-col row

    const int j0 = rA, j1 = rA + 64;
    const int w0 = ((j0 & 3) << 10) + d0 + (j0 >> 2);
    const int w1 = ((j1 & 3) << 10) + d0 + (j1 >> 2);

    float acc[2][4][4];
#pragma unroll
    for (int a = 0; a < 2; ++a)
#pragma unroll
        for (int b = 0; b < 4; ++b)
#pragma unroll
            for (int e = 0; e < 4; ++e) acc[a][b][e] = 0.0f;

    float4 va0, va1, vb0, vb1;

    // ---- prologue: chunk 0 ----
    {
        const float* As = (0 < DIM) ? Xp : Hin;  // chunk 0 -> X / Wx
        va0 = *(const float4*)(Xp  + (size_t)(m0 + rA)      * DIM + c4 * 4);
        va1 = *(const float4*)(Xp  + (size_t)(m0 + rA + 64) * DIM + c4 * 4);
        vb0 = *(const float4*)(Wxl + (size_t)w0 * DIM + c4 * 4);
        vb1 = *(const float4*)(Wxl + (size_t)w1 * DIM + c4 * 4);
        (void)As;
        char* st = smem;
        split_store(st + A_HI, st + A_LO, rA,      c4, va0);
        split_store(st + A_HI, st + A_LO, rA + 64, c4, va1);
        split_store(st + B_HI, st + B_LO, rA,      c4, vb0);
        split_store(st + B_HI, st + B_LO, rA + 64, c4, vb1);
    }
    __syncthreads();

#pragma unroll 1
    for (int i = 0; i < NCHUNK; ++i) {
        // ---- prefetch chunk i+1 into registers ----
        if (i + 1 < NCHUNK) {
            int k = (i + 1) * BK;
            const float* As;
            const float* Bs;
            int kc;
            if (k < DIM) { As = Xp;  Bs = Wxl; kc = k; }
            else         { As = Hin; Bs = Whl; kc = k - DIM; }
            va0 = *(const float4*)(As + (size_t)(m0 + rA)      * DIM + kc + c4 * 4);
            va1 = *(const float4*)(As + (size_t)(m0 + rA + 64) * DIM + kc + c4 * 4);
            vb0 = *(const float4*)(Bs + (size_t)w0 * DIM + kc + c4 * 4);
            vb1 = *(const float4*)(Bs + (size_t)w1 * DIM + kc + c4 * 4);
        }

        // ---- MMA over stage (i&1): 2 k16-steps x 3 split terms ----
        const uint32_t stg = sb + (uint32_t)((i & 1) * STAGE);
#pragma unroll
        for (int s = 0; s < 2; ++s) {
            const uint32_t kb = (uint32_t)(s * 32);
            uint32_t ah[2][4], bh[8], bl[8];

            // A hi fragments (2 m16 tiles)
#pragma unroll
            for (int mt = 0; mt < 2; ++mt) {
                uint32_t addr = stg + A_HI +
                    (uint32_t)((wm * 32 + mt * 16 + l15) * ROWB) + kb + aOff;
                ldm4(ah[mt], addr);
            }
            // B hi fragments (4 n8 tiles via 2 paired x4 loads)
#pragma unroll
            for (int p = 0; p < 2; ++p) {
                uint32_t addr = stg + B_HI +
                    (uint32_t)((wn * 32 + (p * 2 + bSel) * 8 + l7) * ROWB) + kb + bHalf;
                ldm4(bh + p * 4, addr);
            }
            // B lo fragments
#pragma unroll
            for (int p = 0; p < 2; ++p) {
                uint32_t addr = stg + B_LO +
                    (uint32_t)((wn * 32 + (p * 2 + bSel) * 8 + l7) * ROWB) + kb + bHalf;
                ldm4(bl + p * 4, addr);
            }

            // hi*hi and hi*lo
#pragma unroll
            for (int mt = 0; mt < 2; ++mt)
#pragma unroll
                for (int nt = 0; nt < 4; ++nt) {
                    mma16816(acc[mt][nt], ah[mt], bh + nt * 2);
                    mma16816(acc[mt][nt], ah[mt], bl + nt * 2);
                }

            // lo*hi (reuse ah registers for A lo)
#pragma unroll
            for (int mt = 0; mt < 2; ++mt) {
                uint32_t addr = stg + A_LO +
                    (uint32_t)((wm * 32 + mt * 16 + l15) * ROWB) + kb + aOff;
                ldm4(ah[mt], addr);
            }
#pragma unroll
            for (int mt = 0; mt < 2; ++mt)
#pragma unroll
                for (int nt = 0; nt < 4; ++nt)
                    mma16816(acc[mt][nt], ah[mt], bh + nt * 2);
        }

        // ---- convert + store chunk i+1 into the other stage ----
        if (i + 1 < NCHUNK) {
            char* st = smem + ((i + 1) & 1) * STAGE;
            split_store(st + A_HI, st + A_LO, rA,      c4, va0);
            split_store(st + A_HI, st + A_LO, rA + 64, c4, va1);
            split_store(st + B_HI, st + B_LO, rA,      c4, vb0);
            split_store(st + B_HI, st + B_LO, rA + 64, c4, vb1);
        }
        __syncthreads();
    }

    // ========================================================================
    // Epilogue (stage buffers are free now).
    // Thread fragment (mt,nt): rows r,r+8; cols j=wn*32+nt*8+2*tig (+1).
    // tig even -> holds gates {0,1}; tig odd -> gates {2,3}; pair (l, l^1)
    // shares d = wn*8 + nt*2 + (tig>>1). Exchange via shfl.xor(1).
    // ========================================================================
    // stage Cin tile [128 x 32] coalesced
#pragma unroll
    for (int h = 0; h < 2; ++h) {
        int row = (tid >> 3) + h * 64;
        float4 cv = *(const float4*)(Cin + (size_t)(m0 + row) * DIM + d0 + c4 * 4);
        *(float4*)(smem + EP_CIN + row * 128 + c4 * 16) = cv;
    }
    __syncthreads();

    const int grp = lane >> 2;
    const int tig = lane & 3;
    const bool evenT = (tig & 1) == 0;

#pragma unroll
    for (int mt = 0; mt < 2; ++mt)
#pragma unroll
        for (int nt = 0; nt < 4; ++nt) {
            float a0 = acc[mt][nt][0], a1 = acc[mt][nt][1];
            float a2 = acc[mt][nt][2], a3 = acc[mt][nt][3];
            float e0 = __shfl_xor_sync(0xffffffffu, a0, 1);
            float e1 = __shfl_xor_sync(0xffffffffu, a1, 1);
            float e2 = __shfl_xor_sync(0xffffffffu, a2, 1);
            float e3 = __shfl_xor_sync(0xffffffffu, a3, 1);

            int row = wm * 32 + mt * 16 + grp + (evenT ? 0 : 8);
            int dl  = wn * 8 + nt * 2 + (tig >> 1);

            float g0, g1, g2, g3;
            if (evenT) { g0 = a0; g1 = a1; g2 = e0; g3 = e1; }
            else       { g0 = e2; g1 = e3; g2 = a2; g3 = a3; }

            float cprev = *(const float*)(smem + EP_CIN + row * 128 + dl * 4);
            float ig = sigmoidf_(g0);
            float it = tanhf_(g1);
            float fg = sigmoidf_(g2);
            float og = sigmoidf_(g3);
            float c = fg * cprev + ig * it;
            float hv = og * tanhf_(c);
            *(float*)(smem + EP_HS + row * 128 + dl * 4) = hv;
            *(float*)(smem + EP_CS + row * 128 + dl * 4) = c;
        }
    __syncthreads();

    // coalesced writeback
#pragma unroll
    for (int h = 0; h < 2; ++h) {
        int row = (tid >> 3) + h * 64;
        float4 hv = *(const float4*)(smem + EP_HS + row * 128 + c4 * 16);
        float4 cv = *(const float4*)(smem + EP_CS + row * 128 + c4 * 16);
        *(float4*)(Hout + (size_t)(m0 + row) * DIM + d0 + c4 * 4) = hv;
        *(float4*)(Cout + (size_t)(m0 + row) * DIM + d0 + c4 * 4) = cv;
    }
}

// ============================================================================
// kernel_launch
// Inputs: hs[L,B,D] f32, cs[L,B,D] f32, tokens[B] i32, emb[V,D] f32,
//         Wx[L,4D,D] f32, Wh[L,4D,D] f32
// Output: [next_hs (L,B,D) ; next_cs (L,B,D)] f32
// ============================================================================
extern "C" void kernel_launch(void* const* d_in, const int* in_sizes, int n_in,
                              void* d_out, int out_size) {
    (void)in_sizes; (void)n_in; (void)out_size;
    const float* hs     = (const float*)d_in[0];
    const float* cs     = (const float*)d_in[1];
    const int*   tokens = (const int*)d_in[2];
    const float* emb    = (const float*)d_in[3];
    const float* Wx     = (const float*)d_in[4];
    const float* Wh     = (const float*)d_in[5];
    float* out = (float*)d_out;

    cudaFuncSetAttribute(lstm_layer_kernel,
                         cudaFuncAttributeMaxDynamicSharedMemorySize, SMEM_TOTAL);

    const size_t BD = (size_t)BATCH * DIM;
    const size_t WSTRIDE = (size_t)4 * DIM * DIM;

    gather_kernel<<<BATCH, 256>>>(emb, tokens);

    dim3 grid(DIM / (TN / 4), BATCH / TM);   // (32, 32)
    for (int l = 0; l < NLAYER; ++l) {
        const float* X = (l == 0) ? nullptr : (out + (size_t)(l - 1) * BD);
        lstm_layer_kernel<<<grid, THREADS, SMEM_TOTAL>>>(
            X,
            hs + (size_t)l * BD,
            Wx + (size_t)l * WSTRIDE,
            Wh + (size_t)l * WSTRIDE,
            cs + (size_t)l * BD,
            out + (size_t)l * BD,
            out + (size_t)NLAYER * BD + (size_t)l * BD);
    }
}